// round 5
// baseline (speedup 1.0000x reference)
#include <cuda_runtime.h>
#include <cuda_bf16.h>
#include <math.h>
#include <stdint.h>

// Problem constants
#define Bb 4
#define Nn 2048
#define Ff 1024
#define De 128
#define NROWS (Bb*Nn)          // 8192
#define GBLOCK 512             // threads per GEMM CTA

// ---------------------------------------------------------------------------
// Device global scratch (no cudaMalloc allowed)
__device__ __nv_bfloat16 g_feat_hi[(size_t)NROWS * Ff];
__device__ __nv_bfloat16 g_feat_lo[(size_t)NROWS * Ff];
__device__ __nv_bfloat16 g_WT_hi[2][De * Ff];       // W^T [128 x 1024], [0]=Wq,[1]=Wk
__device__ __nv_bfloat16 g_WT_lo[2][De * Ff];
__device__ __nv_bfloat16 g_QK_hi[2][(size_t)NROWS * De];  // [0]=Q,[1]=K
__device__ __nv_bfloat16 g_QK_lo[2][(size_t)NROWS * De];
__device__ float  g_base[(size_t)Bb * Nn * Nn];     // 64 MB
__device__ float  g_c0[NROWS];
__device__ float4 g_cpack[NROWS];                   // c^1..c^4 packed, zero-padded
__device__ float  g_received[4 * NROWS];

// ---------------------------------------------------------------------------
__device__ __forceinline__ uint32_t smem_u32(const void* p) {
    uint32_t a;
    asm("{ .reg .u64 t; cvta.to.shared.u64 t, %1; cvt.u32.u64 %0, t; }" : "=r"(a) : "l"(p));
    return a;
}
__device__ __forceinline__ uint32_t sw128(uint32_t o) { return o ^ ((o >> 3) & 0x70); }

#define CP_ASYNC16(dst_u32, src_gptr) \
    asm volatile("cp.async.cg.shared.global [%0], [%1], 16;" :: "r"(dst_u32), "l"(src_gptr))
#define CP_COMMIT()  asm volatile("cp.async.commit_group;" ::: "memory")
#define CP_WAIT1()   asm volatile("cp.async.wait_group 1;" ::: "memory")
#define CP_WAIT0()   asm volatile("cp.async.wait_group 0;" ::: "memory")

#define LDMATRIX_X4(r0, r1, r2, r3, addr) \
    asm volatile("ldmatrix.sync.aligned.m8n8.x4.shared.b16 {%0,%1,%2,%3}, [%4];" \
        : "=r"(r0), "=r"(r1), "=r"(r2), "=r"(r3) : "r"(addr))

#define MMA_BF16(acc, a, b0v, b1v) \
    asm volatile("mma.sync.aligned.m16n8k16.row.col.f32.bf16.bf16.f32 " \
        "{%0,%1,%2,%3}, {%4,%5,%6,%7}, {%8,%9}, {%0,%1,%2,%3};" \
        : "+f"((acc)[0]), "+f"((acc)[1]), "+f"((acc)[2]), "+f"((acc)[3]) \
        : "r"((a)[0]), "r"((a)[1]), "r"((a)[2]), "r"((a)[3]), "r"(b0v), "r"(b1v))

// ---------------------------------------------------------------------------
// cp.async one 128x64 bf16 tile (rows of 128B) into SW128-swizzled smem
__device__ __forceinline__ void cpasync_tile(
    uint32_t dst_base, const __nv_bfloat16* src, int strideElems, int tid)
{
#pragma unroll
    for (int u = tid; u < 1024; u += GBLOCK) {
        int row = u >> 3, seg = u & 7;
        uint32_t dst = dst_base + sw128((uint32_t)(row * 128 + seg * 16));
        const __nv_bfloat16* g = src + (size_t)row * strideElems + seg * 8;
        CP_ASYNC16(dst, g);
    }
}

// smem buffer layout (per buffer slot, 64KB): AH | AL | BH | BL
#define T_AH 0
#define T_AL 16384
#define T_BH 32768
#define T_BL 49152
#define BUF_BYTES 65536
#define PROJ_SMEM   (3 * BUF_BYTES)   // 3-stage pipeline (192KB)
#define COMPAT_SMEM (2 * BUF_BYTES)   // both K-chunks resident (128KB)

__device__ __forceinline__ void issue_chunk(
    uint32_t sbuf,
    const __nv_bfloat16* Ah, const __nv_bfloat16* Al, int strideA,
    const __nv_bfloat16* Bh, const __nv_bfloat16* Bl, int strideB,
    int c, int tid)
{
    cpasync_tile(sbuf + T_AH, Ah + c * 64, strideA, tid);
    cpasync_tile(sbuf + T_AL, Al + c * 64, strideA, tid);
    cpasync_tile(sbuf + T_BH, Bh + c * 64, strideB, tid);
    cpasync_tile(sbuf + T_BL, Bl + c * 64, strideB, tid);
    CP_COMMIT();
}

// compute one 64-wide K chunk: 3-term bf16 split accumulate.
// 16 warps: 4 in M (32 rows each) x 4 in N (32 cols each); warp tile 32x32.
__device__ __forceinline__ void compute_chunk(uint32_t sbuf, int tid, float acc[2][4][4])
{
    const int lane = tid & 31;
    const int wid = tid >> 5;
    const int wm = wid & 3;        // 4 warps in M
    const int wn = wid >> 2;       // 4 warps in N
    const int q = lane >> 3, r = lane & 7;

    const int a_row = r + ((q & 1) ? 8 : 0);
    const int a_colb = ((q & 2) ? 8 : 0) * 2;
    const int b_row = r + ((q & 2) ? 8 : 0);
    const int b_colb = ((q & 1) ? 8 : 0) * 2;

#pragma unroll
    for (int ks = 0; ks < 4; ks++) {
        const int kb2 = ks * 32;

        uint32_t ah[2][4], al[2][4];
#pragma unroll
        for (int mi = 0; mi < 2; mi++) {
            uint32_t off = sw128((uint32_t)((wm * 32 + mi * 16 + a_row) * 128 + kb2 + a_colb));
            LDMATRIX_X4(ah[mi][0], ah[mi][1], ah[mi][2], ah[mi][3], sbuf + T_AH + off);
            LDMATRIX_X4(al[mi][0], al[mi][1], al[mi][2], al[mi][3], sbuf + T_AL + off);
        }
        uint32_t bh[2][4], bl[2][4];
#pragma unroll
        for (int p = 0; p < 2; p++) {
            uint32_t off = sw128((uint32_t)((wn * 32 + p * 16 + b_row) * 128 + kb2 + b_colb));
            LDMATRIX_X4(bh[p][0], bh[p][1], bh[p][2], bh[p][3], sbuf + T_BH + off);
            LDMATRIX_X4(bl[p][0], bl[p][1], bl[p][2], bl[p][3], sbuf + T_BL + off);
        }
#pragma unroll
        for (int mi = 0; mi < 2; mi++)
#pragma unroll
            for (int ni = 0; ni < 4; ni++) {
                const int p = ni >> 1, s = (ni & 1) * 2;
                MMA_BF16(acc[mi][ni], ah[mi], bh[p][s], bh[p][s + 1]);  // hi*hi
                MMA_BF16(acc[mi][ni], ah[mi], bl[p][s], bl[p][s + 1]);  // hi*lo
                MMA_BF16(acc[mi][ni], al[mi], bh[p][s], bh[p][s + 1]);  // lo*hi
            }
    }
}

// ---------------------------------------------------------------------------
// Fused feature convert + initial charge.
__global__ __launch_bounds__(256) void convert_feat_charge_kernel(
    const float* __restrict__ f, const float* __restrict__ cw, const float* __restrict__ cb)
{
    const int row = blockIdx.x * 8 + (threadIdx.x >> 5);
    const int lane = threadIdx.x & 31;
    const float4* fr = (const float4*)(f + (size_t)row * Ff);
    const float4* cwv = (const float4*)cw;
    __nv_bfloat162* ph = (__nv_bfloat162*)(g_feat_hi + (size_t)row * Ff);
    __nv_bfloat162* pl = (__nv_bfloat162*)(g_feat_lo + (size_t)row * Ff);

    float dot = 0.0f;
#pragma unroll
    for (int u = 0; u < 8; u++) {
        int i = lane + u * 32;
        float4 v = fr[i];
        float4 w = cwv[i];
        dot = fmaf(v.x, w.x, dot); dot = fmaf(v.y, w.y, dot);
        dot = fmaf(v.z, w.z, dot); dot = fmaf(v.w, w.w, dot);
        __nv_bfloat16 h0 = __float2bfloat16(v.x), h1 = __float2bfloat16(v.y);
        __nv_bfloat16 h2 = __float2bfloat16(v.z), h3 = __float2bfloat16(v.w);
        ph[2 * i]     = __halves2bfloat162(h0, h1);
        ph[2 * i + 1] = __halves2bfloat162(h2, h3);
        pl[2 * i]     = __halves2bfloat162(
            __float2bfloat16(v.x - __bfloat162float(h0)),
            __float2bfloat16(v.y - __bfloat162float(h1)));
        pl[2 * i + 1] = __halves2bfloat162(
            __float2bfloat16(v.z - __bfloat162float(h2)),
            __float2bfloat16(v.w - __bfloat162float(h3)));
    }
#pragma unroll
    for (int o = 16; o > 0; o >>= 1) dot += __shfl_xor_sync(0xFFFFFFFFu, dot, o);
    if (lane == 0) g_c0[row] = 1.0f / (1.0f + __expf(-(dot + cb[0])));
}

// ---------------------------------------------------------------------------
// transpose + split W; also zeroes g_received / g_cpack
__global__ void convert_W_kernel(const float* __restrict__ Wq, const float* __restrict__ Wk) {
    const float* W = (blockIdx.y == 0) ? Wq : Wk;
    int idx = blockIdx.x * blockDim.x + threadIdx.x;    // 0..131071
    int e = idx >> 10, fidx = idx & 1023;
    float x = W[(size_t)fidx * De + e];
    __nv_bfloat16 h = __float2bfloat16(x);
    g_WT_hi[blockIdx.y][idx] = h;
    g_WT_lo[blockIdx.y][idx] = __float2bfloat16(x - __bfloat162float(h));
    if (blockIdx.y == 0 && idx < 8 * NROWS) {
        if (idx < 4 * NROWS) g_received[idx] = 0.0f;
        else ((float*)g_cpack)[idx - 4 * NROWS] = 0.0f;
    }
}

// ---------------------------------------------------------------------------
// Projection GEMM: [128x1024] x [1024x128]^T; grid (64, 2), 512 threads.
__global__ __launch_bounds__(GBLOCK, 1) void proj_mma_kernel() {
    extern __shared__ __align__(1024) char smem[];
    const int tid = threadIdx.x;
    const int y = blockIdx.y;
    const int mBase = blockIdx.x * 128;
    uint32_t sb = smem_u32(smem);

    const __nv_bfloat16* Ah = g_feat_hi + (size_t)mBase * Ff;
    const __nv_bfloat16* Al = g_feat_lo + (size_t)mBase * Ff;
    const __nv_bfloat16* Bh = g_WT_hi[y];
    const __nv_bfloat16* Bl = g_WT_lo[y];

    float acc[2][4][4];
#pragma unroll
    for (int mi = 0; mi < 2; mi++)
#pragma unroll
        for (int ni = 0; ni < 4; ni++)
#pragma unroll
            for (int k = 0; k < 4; k++) acc[mi][ni][k] = 0.0f;

    const int CHUNKS = 16;
    issue_chunk(sb + 0 * BUF_BYTES, Ah, Al, Ff, Bh, Bl, Ff, 0, tid);
    issue_chunk(sb + 1 * BUF_BYTES, Ah, Al, Ff, Bh, Bl, Ff, 1, tid);

#pragma unroll 1
    for (int c = 0; c < CHUNKS; c++) {
        if (c < CHUNKS - 1) { CP_WAIT1(); } else { CP_WAIT0(); }
        __syncthreads();
        if (c + 2 < CHUNKS) {
            int buf = (c + 2) % 3;
            issue_chunk(sb + buf * BUF_BYTES, Ah, Al, Ff, Bh, Bl, Ff, c + 2, tid);
        }
        compute_chunk(sb + (c % 3) * BUF_BYTES, tid, acc);
    }

    const int lane = tid & 31, wid = tid >> 5;
    const int wm = wid & 3, wn = wid >> 2;
    const int g = lane >> 2, t2 = (lane & 3) * 2;
    __nv_bfloat16* ph = g_QK_hi[y];
    __nv_bfloat16* pl = g_QK_lo[y];
#pragma unroll
    for (int mi = 0; mi < 2; mi++)
#pragma unroll
        for (int ni = 0; ni < 4; ni++) {
            const int cc = wn * 32 + ni * 8 + t2;
#pragma unroll
            for (int half = 0; half < 2; half++) {
                const int rr = mBase + wm * 32 + mi * 16 + g + half * 8;
                float v0 = acc[mi][ni][half * 2], v1 = acc[mi][ni][half * 2 + 1];
                __nv_bfloat16 h0 = __float2bfloat16(v0), h1 = __float2bfloat16(v1);
                __nv_bfloat16 l0 = __float2bfloat16(v0 - __bfloat162float(h0));
                __nv_bfloat16 l1 = __float2bfloat16(v1 - __bfloat162float(h1));
                *(__nv_bfloat162*)(ph + (size_t)rr * De + cc) = __halves2bfloat162(h0, h1);
                *(__nv_bfloat162*)(pl + (size_t)rr * De + cc) = __halves2bfloat162(l0, l1);
            }
        }
}

// ---------------------------------------------------------------------------
// compat GEMM: base[b,i,j] = Q_i.K_j / sqrt(128) + ls/max(|i-j|,1); 512 threads.
__global__ __launch_bounds__(GBLOCK, 1) void compat_mma_kernel(const float* __restrict__ ls_p) {
    extern __shared__ __align__(1024) char smem[];
    const int tid = threadIdx.x;
    const int b = blockIdx.z;
    const int iBase = blockIdx.y * 128, jBase = blockIdx.x * 128;
    uint32_t sb = smem_u32(smem);

    const __nv_bfloat16* Ah = g_QK_hi[0] + (size_t)(b * Nn + iBase) * De;
    const __nv_bfloat16* Al = g_QK_lo[0] + (size_t)(b * Nn + iBase) * De;
    const __nv_bfloat16* Bh = g_QK_hi[1] + (size_t)(b * Nn + jBase) * De;
    const __nv_bfloat16* Bl = g_QK_lo[1] + (size_t)(b * Nn + jBase) * De;

    issue_chunk(sb + 0 * BUF_BYTES, Ah, Al, De, Bh, Bl, De, 0, tid);
    issue_chunk(sb + 1 * BUF_BYTES, Ah, Al, De, Bh, Bl, De, 1, tid);

    float acc[2][4][4];
#pragma unroll
    for (int mi = 0; mi < 2; mi++)
#pragma unroll
        for (int ni = 0; ni < 4; ni++)
#pragma unroll
            for (int k = 0; k < 4; k++) acc[mi][ni][k] = 0.0f;

    CP_WAIT1();
    __syncthreads();
    compute_chunk(sb + 0 * BUF_BYTES, tid, acc);
    CP_WAIT0();
    __syncthreads();
    compute_chunk(sb + 1 * BUF_BYTES, tid, acc);

    const float ls = *ls_p;
    const float rsqrtD = 0.08838834764831845f;  // 1/sqrt(128)
    const int lane = tid & 31, wid = tid >> 5;
    const int wm = wid & 3, wn = wid >> 2;
    const int g = lane >> 2, t2 = (lane & 3) * 2;
#pragma unroll
    for (int mi = 0; mi < 2; mi++)
#pragma unroll
        for (int ni = 0; ni < 4; ni++) {
            const int col = jBase + wn * 32 + ni * 8 + t2;
#pragma unroll
            for (int half = 0; half < 2; half++) {
                const int row = iBase + wm * 32 + mi * 16 + g + half * 8;
                float d0 = fmaxf(fabsf((float)(row - col)), 1.0f);
                float d1 = fmaxf(fabsf((float)(row - col - 1)), 1.0f);
                float2 v;
                v.x = acc[mi][ni][half * 2]     * rsqrtD + __fdividef(ls, d0);
                v.y = acc[mi][ni][half * 2 + 1] * rsqrtD + __fdividef(ls, d1);
                *(float2*)(g_base + ((size_t)(b * Nn + row)) * Nn + col) = v;
            }
        }
}

// ---------------------------------------------------------------------------
// Softmax pass: logits = base * (1 + ss * dot4(c_i, c_j)); g_cpack zero-padded.
template<bool WRITE_OUT>
__global__ __launch_bounds__(256) void softmax_pass_kernel(
    int s, float* __restrict__ out, const float* __restrict__ ss_p)
{
    __shared__ float s_red[2][8];
    const int b = blockIdx.y;
    const int rowBase = blockIdx.x * 32;
    const int tid = threadIdx.x, lane = tid & 31, wid = tid >> 5;
    const float ss = *ss_p;
    const int j0 = tid * 8;

    float4 cj[8];
#pragma unroll
    for (int t = 0; t < 8; t++) cj[t] = g_cpack[b * Nn + j0 + t];

    float col[8];
#pragma unroll
    for (int t = 0; t < 8; t++) col[t] = 0.0f;

    for (int r = 0; r < 32; r++) {
        const int i = rowBase + r;
        float4 ci = g_cpack[b * Nn + i];
        float cx = ci.x * ss, cy = ci.y * ss, cz = ci.z * ss, cw = ci.w * ss;

        const float4* brow = (const float4*)(g_base + ((size_t)(b * Nn + i)) * Nn + j0);
        float4 b0 = brow[0], b1 = brow[1];
        float bb[8] = {b0.x, b0.y, b0.z, b0.w, b1.x, b1.y, b1.z, b1.w};

        float lv[8];
        float lsum = 0.0f;
#pragma unroll
        for (int t = 0; t < 8; t++) {
            float m = 1.0f;
            m = fmaf(cx, cj[t].x, m);
            m = fmaf(cy, cj[t].y, m);
            m = fmaf(cz, cj[t].z, m);
            m = fmaf(cw, cj[t].w, m);
            float e = __expf(bb[t] * m);
            lv[t] = e;
            lsum += e;
        }
#pragma unroll
        for (int o = 16; o > 0; o >>= 1) lsum += __shfl_xor_sync(0xFFFFFFFFu, lsum, o);
        if (lane == 0) s_red[r & 1][wid] = lsum;
        __syncthreads();
        float tot = s_red[r & 1][0];
#pragma unroll
        for (int w = 1; w < 8; w++) tot += s_red[r & 1][w];
        float inv = __fdividef(1.0f, tot);

        if (WRITE_OUT) {
            float4* orow = (float4*)(out + ((size_t)(b * Nn + i)) * Nn + j0);
            orow[0] = make_float4(lv[0] * inv, lv[1] * inv, lv[2] * inv, lv[3] * inv);
            orow[1] = make_float4(lv[4] * inv, lv[5] * inv, lv[6] * inv, lv[7] * inv);
        } else {
#pragma unroll
            for (int t = 0; t < 8; t++) col[t] = fmaf(lv[t], inv, col[t]);
        }
    }
    if (!WRITE_OUT) {
        float* recv = g_received + (size_t)s * NROWS + b * Nn + j0;
#pragma unroll
        for (int t = 0; t < 8; t++) atomicAdd(&recv[t], col[t]);
    }
}

// ---------------------------------------------------------------------------
// charge update: c^{s+1} = c^s * (1 - decay * sigmoid(received_s - 1))
__global__ void charge_update_kernel(int s, const float* __restrict__ decay_p) {
    int r = blockIdx.x * blockDim.x + threadIdx.x;
    if (r >= NROWS) return;
    float recv = g_received[(size_t)s * NROWS + r];
    float prev = (s == 0) ? g_c0[r] : ((float*)&g_cpack[r])[s - 1];
    float sig = 1.0f / (1.0f + __expf(-(recv - 1.0f)));
    ((float*)&g_cpack[r])[s] = prev * (1.0f - (*decay_p) * sig);
}

// ---------------------------------------------------------------------------
extern "C" void kernel_launch(void* const* d_in, const int* in_sizes, int n_in,
                              void* d_out, int out_size)
{
    const float* features = (const float*)d_in[0];
    const float* W_q      = (const float*)d_in[1];
    const float* W_k      = (const float*)d_in[2];
    const float* charge_w = (const float*)d_in[3];
    const float* charge_b = (const float*)d_in[4];
    const float* ls_p     = (const float*)d_in[5];
    const float* ss_p     = (const float*)d_in[6];
    const float* decay_p  = (const float*)d_in[7];
    float* out = (float*)d_out;

    static bool attr_set = false;
    if (!attr_set) {
        cudaFuncSetAttribute(proj_mma_kernel,   cudaFuncAttributeMaxDynamicSharedMemorySize, PROJ_SMEM);
        cudaFuncSetAttribute(compat_mma_kernel, cudaFuncAttributeMaxDynamicSharedMemorySize, COMPAT_SMEM);
        attr_set = true;
    }

    convert_W_kernel<<<dim3((De * Ff) / 256, 2), 256>>>(W_q, W_k);
    convert_feat_charge_kernel<<<NROWS / 8, 256>>>(features, charge_w, charge_b);

    proj_mma_kernel<<<dim3(NROWS / 128, 2), GBLOCK, PROJ_SMEM>>>();
    compat_mma_kernel<<<dim3(Nn / 128, Nn / 128, Bb), GBLOCK, COMPAT_SMEM>>>(ls_p);

    dim3 sgrid(Nn / 32, Bb);
    for (int s = 0; s < 4; s++) {
        softmax_pass_kernel<false><<<sgrid, 256>>>(s, nullptr, ss_p);
        charge_update_kernel<<<NROWS / 256, 256>>>(s, decay_p);
    }
    softmax_pass_kernel<true><<<sgrid, 256>>>(0, out, ss_p);
}

// round 6
// speedup vs baseline: 1.0795x; 1.0795x over previous
#include <cuda_runtime.h>
#include <cuda_bf16.h>
#include <math.h>
#include <stdint.h>

// Problem constants
#define Bb 4
#define Nn 2048
#define Ff 1024
#define De 128
#define NROWS (Bb*Nn)          // 8192
#define GBLOCK 512             // threads per GEMM CTA

// ---------------------------------------------------------------------------
// Device global scratch (no cudaMalloc allowed)
__device__ __nv_bfloat16 g_feat_hi[(size_t)NROWS * Ff];
__device__ __nv_bfloat16 g_feat_lo[(size_t)NROWS * Ff];
__device__ __nv_bfloat16 g_WT_hi[2][De * Ff];       // W^T [128 x 1024], [0]=Wq,[1]=Wk
__device__ __nv_bfloat16 g_WT_lo[2][De * Ff];
__device__ __nv_bfloat16 g_QK_hi[2][(size_t)NROWS * De];  // [0]=Q,[1]=K
__device__ __nv_bfloat16 g_QK_lo[2][(size_t)NROWS * De];
__device__ float  g_base[(size_t)Bb * Nn * Nn];     // 64 MB
__device__ float  g_c0[NROWS];
__device__ float4 g_cpack[NROWS];                   // c^1..c^4 packed, zero-padded
__device__ float  g_received[4 * NROWS];

// ---------------------------------------------------------------------------
__device__ __forceinline__ uint32_t smem_u32(const void* p) {
    uint32_t a;
    asm("{ .reg .u64 t; cvta.to.shared.u64 t, %1; cvt.u32.u64 %0, t; }" : "=r"(a) : "l"(p));
    return a;
}
__device__ __forceinline__ uint32_t sw128(uint32_t o) { return o ^ ((o >> 3) & 0x70); }

#define CP_ASYNC16(dst_u32, src_gptr) \
    asm volatile("cp.async.cg.shared.global [%0], [%1], 16;" :: "r"(dst_u32), "l"(src_gptr))
#define CP_COMMIT()  asm volatile("cp.async.commit_group;" ::: "memory")
#define CP_WAIT1()   asm volatile("cp.async.wait_group 1;" ::: "memory")
#define CP_WAIT0()   asm volatile("cp.async.wait_group 0;" ::: "memory")

#define LDMATRIX_X4(r0, r1, r2, r3, addr) \
    asm volatile("ldmatrix.sync.aligned.m8n8.x4.shared.b16 {%0,%1,%2,%3}, [%4];" \
        : "=r"(r0), "=r"(r1), "=r"(r2), "=r"(r3) : "r"(addr))

#define MMA_BF16(acc, a, b0v, b1v) \
    asm volatile("mma.sync.aligned.m16n8k16.row.col.f32.bf16.bf16.f32 " \
        "{%0,%1,%2,%3}, {%4,%5,%6,%7}, {%8,%9}, {%0,%1,%2,%3};" \
        : "+f"((acc)[0]), "+f"((acc)[1]), "+f"((acc)[2]), "+f"((acc)[3]) \
        : "r"((a)[0]), "r"((a)[1]), "r"((a)[2]), "r"((a)[3]), "r"(b0v), "r"(b1v))

// ---------------------------------------------------------------------------
// cp.async one 128x64 bf16 tile (rows of 128B) into SW128-swizzled smem
__device__ __forceinline__ void cpasync_tile(
    uint32_t dst_base, const __nv_bfloat16* src, int strideElems, int tid)
{
#pragma unroll
    for (int u = tid; u < 1024; u += GBLOCK) {
        int row = u >> 3, seg = u & 7;
        uint32_t dst = dst_base + sw128((uint32_t)(row * 128 + seg * 16));
        const __nv_bfloat16* g = src + (size_t)row * strideElems + seg * 8;
        CP_ASYNC16(dst, g);
    }
}

// Operand block layout (per 128-row x K=128 operand, hi+lo): 64KB
//   chunk c (c=0,1; 64 K-cols each): HI at c*32768, LO at c*32768+16384
#define OPC_H(c) ((c) * 32768)
#define OPC_L(c) ((c) * 32768 + 16384)
#define OP_BYTES 65536

// load one full operand (128 rows x 128 K, hi+lo) and commit as one group
__device__ __forceinline__ void issue_op(
    uint32_t dst, const __nv_bfloat16* hi, const __nv_bfloat16* lo,
    int strideElems, int tid)
{
#pragma unroll
    for (int c = 0; c < 2; c++) {
        cpasync_tile(dst + OPC_H(c), hi + c * 64, strideElems, tid);
        cpasync_tile(dst + OPC_L(c), lo + c * 64, strideElems, tid);
    }
    CP_COMMIT();
}

// compute full K=128, 3-term bf16 split; A at a_base, B at b_base (both OP layout)
// 16 warps: 4 in M x 4 in N; warp tile 32x32.
__device__ __forceinline__ void compute_tile(
    uint32_t a_base, uint32_t b_base, int tid, float acc[2][4][4])
{
    const int lane = tid & 31;
    const int wid = tid >> 5;
    const int wm = wid & 3;
    const int wn = wid >> 2;
    const int q = lane >> 3, r = lane & 7;

    const int a_row = r + ((q & 1) ? 8 : 0);
    const int a_colb = ((q & 2) ? 8 : 0) * 2;
    const int b_row = r + ((q & 2) ? 8 : 0);
    const int b_colb = ((q & 1) ? 8 : 0) * 2;

#pragma unroll
    for (int c = 0; c < 2; c++) {
#pragma unroll
        for (int ks = 0; ks < 4; ks++) {
            const int kb2 = ks * 32;

            uint32_t ah[2][4], al[2][4];
#pragma unroll
            for (int mi = 0; mi < 2; mi++) {
                uint32_t off = sw128((uint32_t)((wm * 32 + mi * 16 + a_row) * 128 + kb2 + a_colb));
                LDMATRIX_X4(ah[mi][0], ah[mi][1], ah[mi][2], ah[mi][3], a_base + OPC_H(c) + off);
                LDMATRIX_X4(al[mi][0], al[mi][1], al[mi][2], al[mi][3], a_base + OPC_L(c) + off);
            }
            uint32_t bh[2][4], bl[2][4];
#pragma unroll
            for (int p = 0; p < 2; p++) {
                uint32_t off = sw128((uint32_t)((wn * 32 + p * 16 + b_row) * 128 + kb2 + b_colb));
                LDMATRIX_X4(bh[p][0], bh[p][1], bh[p][2], bh[p][3], b_base + OPC_H(c) + off);
                LDMATRIX_X4(bl[p][0], bl[p][1], bl[p][2], bl[p][3], b_base + OPC_L(c) + off);
            }
#pragma unroll
            for (int mi = 0; mi < 2; mi++)
#pragma unroll
                for (int ni = 0; ni < 4; ni++) {
                    const int p = ni >> 1, s = (ni & 1) * 2;
                    MMA_BF16(acc[mi][ni], ah[mi], bh[p][s], bh[p][s + 1]);  // hi*hi
                    MMA_BF16(acc[mi][ni], ah[mi], bl[p][s], bl[p][s + 1]);  // hi*lo
                    MMA_BF16(acc[mi][ni], al[mi], bh[p][s], bh[p][s + 1]);  // lo*hi
                }
        }
    }
}

// ---------------------------------------------------------------------------
// Fused feature convert + initial charge.
__global__ __launch_bounds__(256) void convert_feat_charge_kernel(
    const float* __restrict__ f, const float* __restrict__ cw, const float* __restrict__ cb)
{
    const int row = blockIdx.x * 8 + (threadIdx.x >> 5);
    const int lane = threadIdx.x & 31;
    const float4* fr = (const float4*)(f + (size_t)row * Ff);
    const float4* cwv = (const float4*)cw;
    __nv_bfloat162* ph = (__nv_bfloat162*)(g_feat_hi + (size_t)row * Ff);
    __nv_bfloat162* pl = (__nv_bfloat162*)(g_feat_lo + (size_t)row * Ff);

    float dot = 0.0f;
#pragma unroll
    for (int u = 0; u < 8; u++) {
        int i = lane + u * 32;
        float4 v = fr[i];
        float4 w = cwv[i];
        dot = fmaf(v.x, w.x, dot); dot = fmaf(v.y, w.y, dot);
        dot = fmaf(v.z, w.z, dot); dot = fmaf(v.w, w.w, dot);
        __nv_bfloat16 h0 = __float2bfloat16(v.x), h1 = __float2bfloat16(v.y);
        __nv_bfloat16 h2 = __float2bfloat16(v.z), h3 = __float2bfloat16(v.w);
        ph[2 * i]     = __halves2bfloat162(h0, h1);
        ph[2 * i + 1] = __halves2bfloat162(h2, h3);
        pl[2 * i]     = __halves2bfloat162(
            __float2bfloat16(v.x - __bfloat162float(h0)),
            __float2bfloat16(v.y - __bfloat162float(h1)));
        pl[2 * i + 1] = __halves2bfloat162(
            __float2bfloat16(v.z - __bfloat162float(h2)),
            __float2bfloat16(v.w - __bfloat162float(h3)));
    }
#pragma unroll
    for (int o = 16; o > 0; o >>= 1) dot += __shfl_xor_sync(0xFFFFFFFFu, dot, o);
    if (lane == 0) g_c0[row] = 1.0f / (1.0f + __expf(-(dot + cb[0])));
}

// ---------------------------------------------------------------------------
// transpose + split W; also zeroes g_received / g_cpack
__global__ void convert_W_kernel(const float* __restrict__ Wq, const float* __restrict__ Wk) {
    const float* W = (blockIdx.y == 0) ? Wq : Wk;
    int idx = blockIdx.x * blockDim.x + threadIdx.x;    // 0..131071
    int e = idx >> 10, fidx = idx & 1023;
    float x = W[(size_t)fidx * De + e];
    __nv_bfloat16 h = __float2bfloat16(x);
    g_WT_hi[blockIdx.y][idx] = h;
    g_WT_lo[blockIdx.y][idx] = __float2bfloat16(x - __bfloat162float(h));
    if (blockIdx.y == 0 && idx < 8 * NROWS) {
        if (idx < 4 * NROWS) g_received[idx] = 0.0f;
        else ((float*)g_cpack)[idx - 4 * NROWS] = 0.0f;
    }
}

// ---------------------------------------------------------------------------
// Projection GEMM: [128x1024] x [1024x128]^T; grid (64, 2), 512 threads.
// 3-stage cp.async pipeline over 16 K-chunks (each chunk = OP layout w/ 1 chunk used).
#define PROJ_BUF 65536
#define PROJ_SMEM (3 * PROJ_BUF)
__device__ __forceinline__ void proj_issue_chunk(
    uint32_t sbuf, const __nv_bfloat16* Ah, const __nv_bfloat16* Al,
    const __nv_bfloat16* Bh, const __nv_bfloat16* Bl, int c, int tid)
{
    cpasync_tile(sbuf + 0,     Ah + c * 64, Ff, tid);
    cpasync_tile(sbuf + 16384, Al + c * 64, Ff, tid);
    cpasync_tile(sbuf + 32768, Bh + c * 64, Ff, tid);
    cpasync_tile(sbuf + 49152, Bl + c * 64, Ff, tid);
    CP_COMMIT();
}

__device__ __forceinline__ void proj_compute_chunk(uint32_t sbuf, int tid, float acc[2][4][4])
{
    const int lane = tid & 31;
    const int wid = tid >> 5;
    const int wm = wid & 3, wn = wid >> 2;
    const int q = lane >> 3, r = lane & 7;
    const int a_row = r + ((q & 1) ? 8 : 0);
    const int a_colb = ((q & 2) ? 8 : 0) * 2;
    const int b_row = r + ((q & 2) ? 8 : 0);
    const int b_colb = ((q & 1) ? 8 : 0) * 2;

#pragma unroll
    for (int ks = 0; ks < 4; ks++) {
        const int kb2 = ks * 32;
        uint32_t ah[2][4], al[2][4];
#pragma unroll
        for (int mi = 0; mi < 2; mi++) {
            uint32_t off = sw128((uint32_t)((wm * 32 + mi * 16 + a_row) * 128 + kb2 + a_colb));
            LDMATRIX_X4(ah[mi][0], ah[mi][1], ah[mi][2], ah[mi][3], sbuf + 0 + off);
            LDMATRIX_X4(al[mi][0], al[mi][1], al[mi][2], al[mi][3], sbuf + 16384 + off);
        }
        uint32_t bh[2][4], bl[2][4];
#pragma unroll
        for (int p = 0; p < 2; p++) {
            uint32_t off = sw128((uint32_t)((wn * 32 + p * 16 + b_row) * 128 + kb2 + b_colb));
            LDMATRIX_X4(bh[p][0], bh[p][1], bh[p][2], bh[p][3], sbuf + 32768 + off);
            LDMATRIX_X4(bl[p][0], bl[p][1], bl[p][2], bl[p][3], sbuf + 49152 + off);
        }
#pragma unroll
        for (int mi = 0; mi < 2; mi++)
#pragma unroll
            for (int ni = 0; ni < 4; ni++) {
                const int p = ni >> 1, s = (ni & 1) * 2;
                MMA_BF16(acc[mi][ni], ah[mi], bh[p][s], bh[p][s + 1]);
                MMA_BF16(acc[mi][ni], ah[mi], bl[p][s], bl[p][s + 1]);
                MMA_BF16(acc[mi][ni], al[mi], bh[p][s], bh[p][s + 1]);
            }
    }
}

__global__ __launch_bounds__(GBLOCK, 1) void proj_mma_kernel() {
    extern __shared__ __align__(1024) char smem[];
    const int tid = threadIdx.x;
    const int y = blockIdx.y;
    const int mBase = blockIdx.x * 128;
    uint32_t sb = smem_u32(smem);

    const __nv_bfloat16* Ah = g_feat_hi + (size_t)mBase * Ff;
    const __nv_bfloat16* Al = g_feat_lo + (size_t)mBase * Ff;
    const __nv_bfloat16* Bh = g_WT_hi[y];
    const __nv_bfloat16* Bl = g_WT_lo[y];

    float acc[2][4][4];
#pragma unroll
    for (int mi = 0; mi < 2; mi++)
#pragma unroll
        for (int ni = 0; ni < 4; ni++)
#pragma unroll
            for (int k = 0; k < 4; k++) acc[mi][ni][k] = 0.0f;

    const int CHUNKS = 16;
    proj_issue_chunk(sb + 0 * PROJ_BUF, Ah, Al, Bh, Bl, 0, tid);
    proj_issue_chunk(sb + 1 * PROJ_BUF, Ah, Al, Bh, Bl, 1, tid);

#pragma unroll 1
    for (int c = 0; c < CHUNKS; c++) {
        if (c < CHUNKS - 1) { CP_WAIT1(); } else { CP_WAIT0(); }
        __syncthreads();
        if (c + 2 < CHUNKS) {
            int buf = (c + 2) % 3;
            proj_issue_chunk(sb + buf * PROJ_BUF, Ah, Al, Bh, Bl, c + 2, tid);
        }
        proj_compute_chunk(sb + (c % 3) * PROJ_BUF, tid, acc);
    }

    const int lane = tid & 31, wid = tid >> 5;
    const int wm = wid & 3, wn = wid >> 2;
    const int g = lane >> 2, t2 = (lane & 3) * 2;
    __nv_bfloat16* ph = g_QK_hi[y];
    __nv_bfloat16* pl = g_QK_lo[y];
#pragma unroll
    for (int mi = 0; mi < 2; mi++)
#pragma unroll
        for (int ni = 0; ni < 4; ni++) {
            const int cc = wn * 32 + ni * 8 + t2;
#pragma unroll
            for (int half = 0; half < 2; half++) {
                const int rr = mBase + wm * 32 + mi * 16 + g + half * 8;
                float v0 = acc[mi][ni][half * 2], v1 = acc[mi][ni][half * 2 + 1];
                __nv_bfloat16 h0 = __float2bfloat16(v0), h1 = __float2bfloat16(v1);
                __nv_bfloat16 l0 = __float2bfloat16(v0 - __bfloat162float(h0));
                __nv_bfloat16 l1 = __float2bfloat16(v1 - __bfloat162float(h1));
                *(__nv_bfloat162*)(ph + (size_t)rr * De + cc) = __halves2bfloat162(h0, h1);
                *(__nv_bfloat162*)(pl + (size_t)rr * De + cc) = __halves2bfloat162(l0, l1);
            }
        }
}

// ---------------------------------------------------------------------------
// compat GEMM, persistent-j: grid (2 j-halves, 16 i-tiles, 4 batches) = 128 CTAs.
// A tile resident (64KB); B tiles double-buffered with 1-tile lookahead.
#define COMPAT_SMEM (1024 + 3 * OP_BYTES)   // A + 2 B buffers = 197632
__global__ __launch_bounds__(GBLOCK, 1) void compat_mma_kernel(const float* __restrict__ ls_p) {
    extern __shared__ __align__(1024) char smem[];
    const int tid = threadIdx.x;
    const int jh = blockIdx.x;           // 0..1
    const int iBase = blockIdx.y * 128;  // 16 i-tiles
    const int b = blockIdx.z;
    uint32_t sb = smem_u32(smem);
    const uint32_t A  = sb + 1024;
    const uint32_t B0 = A + OP_BYTES;
    const uint32_t B1 = B0 + OP_BYTES;

    const __nv_bfloat16* Ah = g_QK_hi[0] + (size_t)(b * Nn + iBase) * De;
    const __nv_bfloat16* Al = g_QK_lo[0] + (size_t)(b * Nn + iBase) * De;
    const __nv_bfloat16* Kh = g_QK_hi[1] + (size_t)(b * Nn + jh * 1024) * De;
    const __nv_bfloat16* Kl = g_QK_lo[1] + (size_t)(b * Nn + jh * 1024) * De;

    issue_op(A,  Ah, Al, De, tid);
    issue_op(B0, Kh,            Kl,            De, tid);   // j = 0
    issue_op(B1, Kh + 128 * De, Kl + 128 * De, De, tid);   // j = 1
    CP_WAIT1();          // A and B0 complete
    __syncthreads();

    const float ls = *ls_p;
    const float rsqrtD = 0.08838834764831845f;  // 1/sqrt(128)
    const int lane = tid & 31, wid = tid >> 5;
    const int wm = wid & 3, wn = wid >> 2;
    const int g = lane >> 2, t2 = (lane & 3) * 2;

#pragma unroll 1
    for (int j = 0; j < 8; j++) {
        const uint32_t Bcur = (j & 1) ? B1 : B0;

        float acc[2][4][4];
#pragma unroll
        for (int mi = 0; mi < 2; mi++)
#pragma unroll
            for (int ni = 0; ni < 4; ni++)
#pragma unroll
                for (int k = 0; k < 4; k++) acc[mi][ni][k] = 0.0f;

        compute_tile(A, Bcur, tid, acc);

        // epilogue for this j tile (registers only, no smem)
        const int jBase = jh * 1024 + j * 128;
#pragma unroll
        for (int mi = 0; mi < 2; mi++)
#pragma unroll
            for (int ni = 0; ni < 4; ni++) {
                const int col = jBase + wn * 32 + ni * 8 + t2;
#pragma unroll
                for (int half = 0; half < 2; half++) {
                    const int row = iBase + wm * 32 + mi * 16 + g + half * 8;
                    float d0 = fmaxf(fabsf((float)(row - col)), 1.0f);
                    float d1 = fmaxf(fabsf((float)(row - col - 1)), 1.0f);
                    float2 v;
                    v.x = acc[mi][ni][half * 2]     * rsqrtD + __fdividef(ls, d0);
                    v.y = acc[mi][ni][half * 2 + 1] * rsqrtD + __fdividef(ls, d1);
                    *(float2*)(g_base + ((size_t)(b * Nn + row)) * Nn + col) = v;
                }
            }

        __syncthreads();                       // all warps done reading Bcur
        if (j + 2 < 8) {
            issue_op(Bcur, Kh + (size_t)(j + 2) * 128 * De,
                           Kl + (size_t)(j + 2) * 128 * De, De, tid);
            CP_WAIT1();                        // B(j+1) complete
            __syncthreads();
        } else if (j + 1 < 8) {
            CP_WAIT0();                        // last B complete
            __syncthreads();
        }
    }
}

// ---------------------------------------------------------------------------
// Softmax pass: logits = base * (1 + ss * dot4(c_i, c_j)); g_cpack zero-padded.
// Next-row prefetch to raise MLP.
template<bool WRITE_OUT>
__global__ __launch_bounds__(256) void softmax_pass_kernel(
    int s, float* __restrict__ out, const float* __restrict__ ss_p)
{
    __shared__ float s_red[2][8];
    const int b = blockIdx.y;
    const int rowBase = blockIdx.x * 32;
    const int tid = threadIdx.x, lane = tid & 31, wid = tid >> 5;
    const float ss = *ss_p;
    const int j0 = tid * 8;

    float4 cj[8];
#pragma unroll
    for (int t = 0; t < 8; t++) cj[t] = g_cpack[b * Nn + j0 + t];

    float col[8];
#pragma unroll
    for (int t = 0; t < 8; t++) col[t] = 0.0f;

    const float4* brow0 = (const float4*)(g_base + ((size_t)(b * Nn + rowBase)) * Nn + j0);
    float4 p0 = brow0[0], p1 = brow0[1];

    for (int r = 0; r < 32; r++) {
        const int i = rowBase + r;
        float4 ci = g_cpack[b * Nn + i];
        float cx = ci.x * ss, cy = ci.y * ss, cz = ci.z * ss, cw = ci.w * ss;

        float4 b0 = p0, b1 = p1;
        if (r + 1 < 32) {
            const float4* nb = (const float4*)(g_base + ((size_t)(b * Nn + i + 1)) * Nn + j0);
            p0 = nb[0]; p1 = nb[1];
        }
        float bb[8] = {b0.x, b0.y, b0.z, b0.w, b1.x, b1.y, b1.z, b1.w};

        float lv[8];
        float lsum = 0.0f;
#pragma unroll
        for (int t = 0; t < 8; t++) {
            float m = 1.0f;
            m = fmaf(cx, cj[t].x, m);
            m = fmaf(cy, cj[t].y, m);
            m = fmaf(cz, cj[t].z, m);
            m = fmaf(cw, cj[t].w, m);
            float e = __expf(bb[t] * m);
            lv[t] = e;
            lsum += e;
        }
#pragma unroll
        for (int o = 16; o > 0; o >>= 1) lsum += __shfl_xor_sync(0xFFFFFFFFu, lsum, o);
        if (lane == 0) s_red[r & 1][wid] = lsum;
        __syncthreads();
        float tot = s_red[r & 1][0];
#pragma unroll
        for (int w = 1; w < 8; w++) tot += s_red[r & 1][w];
        float inv = __fdividef(1.0f, tot);

        if (WRITE_OUT) {
            float4* orow = (float4*)(out + ((size_t)(b * Nn + i)) * Nn + j0);
            orow[0] = make_float4(lv[0] * inv, lv[1] * inv, lv[2] * inv, lv[3] * inv);
            orow[1] = make_float4(lv[4] * inv, lv[5] * inv, lv[6] * inv, lv[7] * inv);
        } else {
#pragma unroll
            for (int t = 0; t < 8; t++) col[t] = fmaf(lv[t], inv, col[t]);
        }
    }
    if (!WRITE_OUT) {
        float* recv = g_received + (size_t)s * NROWS + b * Nn + j0;
#pragma unroll
        for (int t = 0; t < 8; t++) atomicAdd(&recv[t], col[t]);
    }
}

// ---------------------------------------------------------------------------
// charge update: c^{s+1} = c^s * (1 - decay * sigmoid(received_s - 1))
__global__ void charge_update_kernel(int s, const float* __restrict__ decay_p) {
    int r = blockIdx.x * blockDim.x + threadIdx.x;
    if (r >= NROWS) return;
    float recv = g_received[(size_t)s * NROWS + r];
    float prev = (s == 0) ? g_c0[r] : ((float*)&g_cpack[r])[s - 1];
    float sig = 1.0f / (1.0f + __expf(-(recv - 1.0f)));
    ((float*)&g_cpack[r])[s] = prev * (1.0f - (*decay_p) * sig);
}

// ---------------------------------------------------------------------------
extern "C" void kernel_launch(void* const* d_in, const int* in_sizes, int n_in,
                              void* d_out, int out_size)
{
    const float* features = (const float*)d_in[0];
    const float* W_q      = (const float*)d_in[1];
    const float* W_k      = (const float*)d_in[2];
    const float* charge_w = (const float*)d_in[3];
    const float* charge_b = (const float*)d_in[4];
    const float* ls_p     = (const float*)d_in[5];
    const float* ss_p     = (const float*)d_in[6];
    const float* decay_p  = (const float*)d_in[7];
    float* out = (float*)d_out;

    static bool attr_set = false;
    if (!attr_set) {
        cudaFuncSetAttribute(proj_mma_kernel,   cudaFuncAttributeMaxDynamicSharedMemorySize, PROJ_SMEM);
        cudaFuncSetAttribute(compat_mma_kernel, cudaFuncAttributeMaxDynamicSharedMemorySize, COMPAT_SMEM);
        attr_set = true;
    }

    convert_W_kernel<<<dim3((De * Ff) / 256, 2), 256>>>(W_q, W_k);
    convert_feat_charge_kernel<<<NROWS / 8, 256>>>(features, charge_w, charge_b);

    proj_mma_kernel<<<dim3(NROWS / 128, 2), GBLOCK, PROJ_SMEM>>>();
    compat_mma_kernel<<<dim3(2, 16, Bb), GBLOCK, COMPAT_SMEM>>>(ls_p);

    dim3 sgrid(Nn / 32, Bb);
    for (int s = 0; s < 4; s++) {
        softmax_pass_kernel<false><<<sgrid, 256>>>(s, nullptr, ss_p);
        charge_update_kernel<<<NROWS / 256, 256>>>(s, decay_p);
    }
    softmax_pass_kernel<true><<<sgrid, 256>>>(0, out, ss_p);
}

// round 7
// speedup vs baseline: 1.0888x; 1.0086x over previous
#include <cuda_runtime.h>
#include <cuda_bf16.h>
#include <math.h>
#include <stdint.h>

// Problem constants
#define Bb 4
#define Nn 2048
#define Ff 1024
#define De 128
#define NROWS (Bb*Nn)          // 8192
#define GBLOCK 256             // threads per GEMM CTA (8 warps)

// ---------------------------------------------------------------------------
// Device global scratch (no cudaMalloc allowed)
__device__ __nv_bfloat16 g_feat_hi[(size_t)NROWS * Ff];
__device__ __nv_bfloat16 g_feat_lo[(size_t)NROWS * Ff];
__device__ __nv_bfloat16 g_WT_hi[2][De * Ff];       // W^T [128 x 1024], [0]=Wq,[1]=Wk
__device__ __nv_bfloat16 g_WT_lo[2][De * Ff];
__device__ __nv_bfloat16 g_QK_hi[2][(size_t)NROWS * De];  // [0]=Q,[1]=K
__device__ __nv_bfloat16 g_QK_lo[2][(size_t)NROWS * De];
__device__ float  g_base[(size_t)Bb * Nn * Nn];     // 64 MB
__device__ float  g_c0[NROWS];
__device__ float4 g_cpack[NROWS];                   // c^1..c^4 packed, zero-padded
__device__ float  g_received[4 * NROWS];

// ---------------------------------------------------------------------------
__device__ __forceinline__ uint32_t smem_u32(const void* p) {
    uint32_t a;
    asm("{ .reg .u64 t; cvta.to.shared.u64 t, %1; cvt.u32.u64 %0, t; }" : "=r"(a) : "l"(p));
    return a;
}
__device__ __forceinline__ uint32_t sw128(uint32_t o) { return o ^ ((o >> 3) & 0x70); }

#define CP_ASYNC16(dst_u32, src_gptr) \
    asm volatile("cp.async.cg.shared.global [%0], [%1], 16;" :: "r"(dst_u32), "l"(src_gptr))
#define CP_COMMIT()  asm volatile("cp.async.commit_group;" ::: "memory")
#define CP_WAIT1()   asm volatile("cp.async.wait_group 1;" ::: "memory")
#define CP_WAIT0()   asm volatile("cp.async.wait_group 0;" ::: "memory")

#define LDMATRIX_X4(r0, r1, r2, r3, addr) \
    asm volatile("ldmatrix.sync.aligned.m8n8.x4.shared.b16 {%0,%1,%2,%3}, [%4];" \
        : "=r"(r0), "=r"(r1), "=r"(r2), "=r"(r3) : "r"(addr))

#define MMA_BF16(acc, a, b0v, b1v) \
    asm volatile("mma.sync.aligned.m16n8k16.row.col.f32.bf16.bf16.f32 " \
        "{%0,%1,%2,%3}, {%4,%5,%6,%7}, {%8,%9}, {%0,%1,%2,%3};" \
        : "+f"((acc)[0]), "+f"((acc)[1]), "+f"((acc)[2]), "+f"((acc)[3]) \
        : "r"((a)[0]), "r"((a)[1]), "r"((a)[2]), "r"((a)[3]), "r"(b0v), "r"(b1v))

// ---------------------------------------------------------------------------
// cp.async one 128x64 bf16 tile (rows of 128B) into SW128-swizzled smem
__device__ __forceinline__ void cpasync_tile(
    uint32_t dst_base, const __nv_bfloat16* src, int strideElems, int tid)
{
#pragma unroll
    for (int u = tid; u < 1024; u += GBLOCK) {
        int row = u >> 3, seg = u & 7;
        uint32_t dst = dst_base + sw128((uint32_t)(row * 128 + seg * 16));
        const __nv_bfloat16* g = src + (size_t)row * strideElems + seg * 8;
        CP_ASYNC16(dst, g);
    }
}

// Operand block layout (per 128-row x K=128 operand, hi+lo): 64KB
//   chunk c (c=0,1; 64 K-cols each): HI at c*32768, LO at c*32768+16384
#define OPC_H(c) ((c) * 32768)
#define OPC_L(c) ((c) * 32768 + 16384)
#define OP_BYTES 65536

// load one full operand (128 rows x 128 K, hi+lo) and commit as one group
__device__ __forceinline__ void issue_op(
    uint32_t dst, const __nv_bfloat16* hi, const __nv_bfloat16* lo,
    int strideElems, int tid)
{
#pragma unroll
    for (int c = 0; c < 2; c++) {
        cpasync_tile(dst + OPC_H(c), hi + c * 64, strideElems, tid);
        cpasync_tile(dst + OPC_L(c), lo + c * 64, strideElems, tid);
    }
    CP_COMMIT();
}

// compute full K=128, 3-term bf16 split; A at a_base, B at b_base (OP layout).
// 8 warps: 2 in M (64 rows) x 4 in N (32 cols); warp tile 64x32.
__device__ __forceinline__ void compute_tile(
    uint32_t a_base, uint32_t b_base, int tid, float acc[4][4][4])
{
    const int lane = tid & 31;
    const int wid = tid >> 5;
    const int wm = wid & 1;        // 2 warps in M
    const int wn = wid >> 1;       // 4 warps in N
    const int q = lane >> 3, r = lane & 7;

    const int a_row = r + ((q & 1) ? 8 : 0);
    const int a_colb = ((q & 2) ? 8 : 0) * 2;
    const int b_row = r + ((q & 2) ? 8 : 0);
    const int b_colb = ((q & 1) ? 8 : 0) * 2;

#pragma unroll
    for (int c = 0; c < 2; c++) {
#pragma unroll
        for (int ks = 0; ks < 4; ks++) {
            const int kb2 = ks * 32;

            uint32_t ah[4][4], al[4][4];
#pragma unroll
            for (int mi = 0; mi < 4; mi++) {
                uint32_t off = sw128((uint32_t)((wm * 64 + mi * 16 + a_row) * 128 + kb2 + a_colb));
                LDMATRIX_X4(ah[mi][0], ah[mi][1], ah[mi][2], ah[mi][3], a_base + OPC_H(c) + off);
                LDMATRIX_X4(al[mi][0], al[mi][1], al[mi][2], al[mi][3], a_base + OPC_L(c) + off);
            }
            uint32_t bh[2][4], bl[2][4];
#pragma unroll
            for (int p = 0; p < 2; p++) {
                uint32_t off = sw128((uint32_t)((wn * 32 + p * 16 + b_row) * 128 + kb2 + b_colb));
                LDMATRIX_X4(bh[p][0], bh[p][1], bh[p][2], bh[p][3], b_base + OPC_H(c) + off);
                LDMATRIX_X4(bl[p][0], bl[p][1], bl[p][2], bl[p][3], b_base + OPC_L(c) + off);
            }
#pragma unroll
            for (int mi = 0; mi < 4; mi++)
#pragma unroll
                for (int ni = 0; ni < 4; ni++) {
                    const int p = ni >> 1, s = (ni & 1) * 2;
                    MMA_BF16(acc[mi][ni], ah[mi], bh[p][s], bh[p][s + 1]);  // hi*hi
                    MMA_BF16(acc[mi][ni], ah[mi], bl[p][s], bl[p][s + 1]);  // hi*lo
                    MMA_BF16(acc[mi][ni], al[mi], bh[p][s], bh[p][s + 1]);  // lo*hi
                }
        }
    }
}

// ---------------------------------------------------------------------------
// Fused feature convert + initial charge.
__global__ __launch_bounds__(256) void convert_feat_charge_kernel(
    const float* __restrict__ f, const float* __restrict__ cw, const float* __restrict__ cb)
{
    const int row = blockIdx.x * 8 + (threadIdx.x >> 5);
    const int lane = threadIdx.x & 31;
    const float4* fr = (const float4*)(f + (size_t)row * Ff);
    const float4* cwv = (const float4*)cw;
    __nv_bfloat162* ph = (__nv_bfloat162*)(g_feat_hi + (size_t)row * Ff);
    __nv_bfloat162* pl = (__nv_bfloat162*)(g_feat_lo + (size_t)row * Ff);

    float dot = 0.0f;
#pragma unroll
    for (int u = 0; u < 8; u++) {
        int i = lane + u * 32;
        float4 v = fr[i];
        float4 w = cwv[i];
        dot = fmaf(v.x, w.x, dot); dot = fmaf(v.y, w.y, dot);
        dot = fmaf(v.z, w.z, dot); dot = fmaf(v.w, w.w, dot);
        __nv_bfloat16 h0 = __float2bfloat16(v.x), h1 = __float2bfloat16(v.y);
        __nv_bfloat16 h2 = __float2bfloat16(v.z), h3 = __float2bfloat16(v.w);
        ph[2 * i]     = __halves2bfloat162(h0, h1);
        ph[2 * i + 1] = __halves2bfloat162(h2, h3);
        pl[2 * i]     = __halves2bfloat162(
            __float2bfloat16(v.x - __bfloat162float(h0)),
            __float2bfloat16(v.y - __bfloat162float(h1)));
        pl[2 * i + 1] = __halves2bfloat162(
            __float2bfloat16(v.z - __bfloat162float(h2)),
            __float2bfloat16(v.w - __bfloat162float(h3)));
    }
#pragma unroll
    for (int o = 16; o > 0; o >>= 1) dot += __shfl_xor_sync(0xFFFFFFFFu, dot, o);
    if (lane == 0) g_c0[row] = 1.0f / (1.0f + __expf(-(dot + cb[0])));
}

// ---------------------------------------------------------------------------
// transpose + split W; also zeroes g_received / g_cpack
__global__ void convert_W_kernel(const float* __restrict__ Wq, const float* __restrict__ Wk) {
    const float* W = (blockIdx.y == 0) ? Wq : Wk;
    int idx = blockIdx.x * blockDim.x + threadIdx.x;    // 0..131071
    int e = idx >> 10, fidx = idx & 1023;
    float x = W[(size_t)fidx * De + e];
    __nv_bfloat16 h = __float2bfloat16(x);
    g_WT_hi[blockIdx.y][idx] = h;
    g_WT_lo[blockIdx.y][idx] = __float2bfloat16(x - __bfloat162float(h));
    if (blockIdx.y == 0 && idx < 8 * NROWS) {
        if (idx < 4 * NROWS) g_received[idx] = 0.0f;
        else ((float*)g_cpack)[idx - 4 * NROWS] = 0.0f;
    }
}

// ---------------------------------------------------------------------------
// Projection GEMM: [128x1024] x [1024x128]^T; grid (64, 2), 256 threads.
// 3-stage cp.async pipeline over 16 K-chunks.
#define PROJ_BUF 65536
#define PROJ_SMEM (3 * PROJ_BUF)
__device__ __forceinline__ void proj_issue_chunk(
    uint32_t sbuf, const __nv_bfloat16* Ah, const __nv_bfloat16* Al,
    const __nv_bfloat16* Bh, const __nv_bfloat16* Bl, int c, int tid)
{
    cpasync_tile(sbuf + 0,     Ah + c * 64, Ff, tid);
    cpasync_tile(sbuf + 16384, Al + c * 64, Ff, tid);
    cpasync_tile(sbuf + 32768, Bh + c * 64, Ff, tid);
    cpasync_tile(sbuf + 49152, Bl + c * 64, Ff, tid);
    CP_COMMIT();
}

__device__ __forceinline__ void proj_compute_chunk(uint32_t sbuf, int tid, float acc[4][4][4])
{
    const int lane = tid & 31;
    const int wid = tid >> 5;
    const int wm = wid & 1, wn = wid >> 1;
    const int q = lane >> 3, r = lane & 7;
    const int a_row = r + ((q & 1) ? 8 : 0);
    const int a_colb = ((q & 2) ? 8 : 0) * 2;
    const int b_row = r + ((q & 2) ? 8 : 0);
    const int b_colb = ((q & 1) ? 8 : 0) * 2;

#pragma unroll
    for (int ks = 0; ks < 4; ks++) {
        const int kb2 = ks * 32;
        uint32_t ah[4][4], al[4][4];
#pragma unroll
        for (int mi = 0; mi < 4; mi++) {
            uint32_t off = sw128((uint32_t)((wm * 64 + mi * 16 + a_row) * 128 + kb2 + a_colb));
            LDMATRIX_X4(ah[mi][0], ah[mi][1], ah[mi][2], ah[mi][3], sbuf + 0 + off);
            LDMATRIX_X4(al[mi][0], al[mi][1], al[mi][2], al[mi][3], sbuf + 16384 + off);
        }
        uint32_t bh[2][4], bl[2][4];
#pragma unroll
        for (int p = 0; p < 2; p++) {
            uint32_t off = sw128((uint32_t)((wn * 32 + p * 16 + b_row) * 128 + kb2 + b_colb));
            LDMATRIX_X4(bh[p][0], bh[p][1], bh[p][2], bh[p][3], sbuf + 32768 + off);
            LDMATRIX_X4(bl[p][0], bl[p][1], bl[p][2], bl[p][3], sbuf + 49152 + off);
        }
#pragma unroll
        for (int mi = 0; mi < 4; mi++)
#pragma unroll
            for (int ni = 0; ni < 4; ni++) {
                const int p = ni >> 1, s = (ni & 1) * 2;
                MMA_BF16(acc[mi][ni], ah[mi], bh[p][s], bh[p][s + 1]);
                MMA_BF16(acc[mi][ni], ah[mi], bl[p][s], bl[p][s + 1]);
                MMA_BF16(acc[mi][ni], al[mi], bh[p][s], bh[p][s + 1]);
            }
    }
}

__global__ __launch_bounds__(GBLOCK, 1) void proj_mma_kernel() {
    extern __shared__ __align__(1024) char smem[];
    const int tid = threadIdx.x;
    const int y = blockIdx.y;
    const int mBase = blockIdx.x * 128;
    uint32_t sb = smem_u32(smem);

    const __nv_bfloat16* Ah = g_feat_hi + (size_t)mBase * Ff;
    const __nv_bfloat16* Al = g_feat_lo + (size_t)mBase * Ff;
    const __nv_bfloat16* Bh = g_WT_hi[y];
    const __nv_bfloat16* Bl = g_WT_lo[y];

    float acc[4][4][4];
#pragma unroll
    for (int mi = 0; mi < 4; mi++)
#pragma unroll
        for (int ni = 0; ni < 4; ni++)
#pragma unroll
            for (int k = 0; k < 4; k++) acc[mi][ni][k] = 0.0f;

    const int CHUNKS = 16;
    proj_issue_chunk(sb + 0 * PROJ_BUF, Ah, Al, Bh, Bl, 0, tid);
    proj_issue_chunk(sb + 1 * PROJ_BUF, Ah, Al, Bh, Bl, 1, tid);

#pragma unroll 1
    for (int c = 0; c < CHUNKS; c++) {
        if (c < CHUNKS - 1) { CP_WAIT1(); } else { CP_WAIT0(); }
        __syncthreads();
        if (c + 2 < CHUNKS) {
            int buf = (c + 2) % 3;
            proj_issue_chunk(sb + buf * PROJ_BUF, Ah, Al, Bh, Bl, c + 2, tid);
        }
        proj_compute_chunk(sb + (c % 3) * PROJ_BUF, tid, acc);
    }

    const int lane = tid & 31, wid = tid >> 5;
    const int wm = wid & 1, wn = wid >> 1;
    const int g = lane >> 2, t2 = (lane & 3) * 2;
    __nv_bfloat16* ph = g_QK_hi[y];
    __nv_bfloat16* pl = g_QK_lo[y];
#pragma unroll
    for (int mi = 0; mi < 4; mi++)
#pragma unroll
        for (int ni = 0; ni < 4; ni++) {
            const int cc = wn * 32 + ni * 8 + t2;
#pragma unroll
            for (int half = 0; half < 2; half++) {
                const int rr = mBase + wm * 64 + mi * 16 + g + half * 8;
                float v0 = acc[mi][ni][half * 2], v1 = acc[mi][ni][half * 2 + 1];
                __nv_bfloat16 h0 = __float2bfloat16(v0), h1 = __float2bfloat16(v1);
                __nv_bfloat16 l0 = __float2bfloat16(v0 - __bfloat162float(h0));
                __nv_bfloat16 l1 = __float2bfloat16(v1 - __bfloat162float(h1));
                *(__nv_bfloat162*)(ph + (size_t)rr * De + cc) = __halves2bfloat162(h0, h1);
                *(__nv_bfloat162*)(pl + (size_t)rr * De + cc) = __halves2bfloat162(l0, l1);
            }
        }
}

// ---------------------------------------------------------------------------
// compat GEMM, persistent-j: grid (2 j-halves, 16 i-tiles, 4 batches) = 128 CTAs.
// A tile resident (64KB); B tiles double-buffered with 1-tile lookahead.
#define COMPAT_SMEM (1024 + 3 * OP_BYTES)   // A + 2 B buffers = 197632
__global__ __launch_bounds__(GBLOCK, 1) void compat_mma_kernel(const float* __restrict__ ls_p) {
    extern __shared__ __align__(1024) char smem[];
    const int tid = threadIdx.x;
    const int jh = blockIdx.x;           // 0..1
    const int iBase = blockIdx.y * 128;  // 16 i-tiles
    const int b = blockIdx.z;
    uint32_t sb = smem_u32(smem);
    const uint32_t A  = sb + 1024;
    const uint32_t B0 = A + OP_BYTES;
    const uint32_t B1 = B0 + OP_BYTES;

    const __nv_bfloat16* Ah = g_QK_hi[0] + (size_t)(b * Nn + iBase) * De;
    const __nv_bfloat16* Al = g_QK_lo[0] + (size_t)(b * Nn + iBase) * De;
    const __nv_bfloat16* Kh = g_QK_hi[1] + (size_t)(b * Nn + jh * 1024) * De;
    const __nv_bfloat16* Kl = g_QK_lo[1] + (size_t)(b * Nn + jh * 1024) * De;

    issue_op(A,  Ah, Al, De, tid);
    issue_op(B0, Kh,            Kl,            De, tid);   // j = 0
    issue_op(B1, Kh + 128 * De, Kl + 128 * De, De, tid);   // j = 1
    CP_WAIT1();          // A and B0 complete
    __syncthreads();

    const float ls = *ls_p;
    const float rsqrtD = 0.08838834764831845f;  // 1/sqrt(128)
    const int lane = tid & 31, wid = tid >> 5;
    const int wm = wid & 1, wn = wid >> 1;
    const int g = lane >> 2, t2 = (lane & 3) * 2;

#pragma unroll 1
    for (int j = 0; j < 8; j++) {
        const uint32_t Bcur = (j & 1) ? B1 : B0;

        float acc[4][4][4];
#pragma unroll
        for (int mi = 0; mi < 4; mi++)
#pragma unroll
            for (int ni = 0; ni < 4; ni++)
#pragma unroll
                for (int k = 0; k < 4; k++) acc[mi][ni][k] = 0.0f;

        compute_tile(A, Bcur, tid, acc);

        // epilogue for this j tile (registers only, no smem)
        const int jBase = jh * 1024 + j * 128;
#pragma unroll
        for (int mi = 0; mi < 4; mi++)
#pragma unroll
            for (int ni = 0; ni < 4; ni++) {
                const int col = jBase + wn * 32 + ni * 8 + t2;
#pragma unroll
                for (int half = 0; half < 2; half++) {
                    const int row = iBase + wm * 64 + mi * 16 + g + half * 8;
                    float d0 = fmaxf(fabsf((float)(row - col)), 1.0f);
                    float d1 = fmaxf(fabsf((float)(row - col - 1)), 1.0f);
                    float2 v;
                    v.x = acc[mi][ni][half * 2]     * rsqrtD + __fdividef(ls, d0);
                    v.y = acc[mi][ni][half * 2 + 1] * rsqrtD + __fdividef(ls, d1);
                    *(float2*)(g_base + ((size_t)(b * Nn + row)) * Nn + col) = v;
                }
            }

        __syncthreads();                       // all warps done reading Bcur
        if (j + 2 < 8) {
            issue_op(Bcur, Kh + (size_t)(j + 2) * 128 * De,
                           Kl + (size_t)(j + 2) * 128 * De, De, tid);
            CP_WAIT1();                        // B(j+1) complete
            __syncthreads();
        } else if (j + 1 < 8) {
            CP_WAIT0();                        // last B complete
            __syncthreads();
        }
    }
}

// ---------------------------------------------------------------------------
// Softmax pass: logits = base * (1 + ss * dot4(c_i, c_j)); g_cpack zero-padded.
// Next-row prefetch to raise MLP.
template<bool WRITE_OUT>
__global__ __launch_bounds__(256) void softmax_pass_kernel(
    int s, float* __restrict__ out, const float* __restrict__ ss_p)
{
    __shared__ float s_red[2][8];
    const int b = blockIdx.y;
    const int rowBase = blockIdx.x * 32;
    const int tid = threadIdx.x, lane = tid & 31, wid = tid >> 5;
    const float ss = *ss_p;
    const int j0 = tid * 8;

    float4 cj[8];
#pragma unroll
    for (int t = 0; t < 8; t++) cj[t] = g_cpack[b * Nn + j0 + t];

    float col[8];
#pragma unroll
    for (int t = 0; t < 8; t++) col[t] = 0.0f;

    const float4* brow0 = (const float4*)(g_base + ((size_t)(b * Nn + rowBase)) * Nn + j0);
    float4 p0 = brow0[0], p1 = brow0[1];

    for (int r = 0; r < 32; r++) {
        const int i = rowBase + r;
        float4 ci = g_cpack[b * Nn + i];
        float cx = ci.x * ss, cy = ci.y * ss, cz = ci.z * ss, cw = ci.w * ss;

        float4 b0 = p0, b1 = p1;
        if (r + 1 < 32) {
            const float4* nb = (const float4*)(g_base + ((size_t)(b * Nn + i + 1)) * Nn + j0);
            p0 = nb[0]; p1 = nb[1];
        }
        float bb[8] = {b0.x, b0.y, b0.z, b0.w, b1.x, b1.y, b1.z, b1.w};

        float lv[8];
        float lsum = 0.0f;
#pragma unroll
        for (int t = 0; t < 8; t++) {
            float m = 1.0f;
            m = fmaf(cx, cj[t].x, m);
            m = fmaf(cy, cj[t].y, m);
            m = fmaf(cz, cj[t].z, m);
            m = fmaf(cw, cj[t].w, m);
            float e = __expf(bb[t] * m);
            lv[t] = e;
            lsum += e;
        }
#pragma unroll
        for (int o = 16; o > 0; o >>= 1) lsum += __shfl_xor_sync(0xFFFFFFFFu, lsum, o);
        if (lane == 0) s_red[r & 1][wid] = lsum;
        __syncthreads();
        float tot = s_red[r & 1][0];
#pragma unroll
        for (int w = 1; w < 8; w++) tot += s_red[r & 1][w];
        float inv = __fdividef(1.0f, tot);

        if (WRITE_OUT) {
            float4* orow = (float4*)(out + ((size_t)(b * Nn + i)) * Nn + j0);
            orow[0] = make_float4(lv[0] * inv, lv[1] * inv, lv[2] * inv, lv[3] * inv);
            orow[1] = make_float4(lv[4] * inv, lv[5] * inv, lv[6] * inv, lv[7] * inv);
        } else {
#pragma unroll
            for (int t = 0; t < 8; t++) col[t] = fmaf(lv[t], inv, col[t]);
        }
    }
    if (!WRITE_OUT) {
        float* recv = g_received + (size_t)s * NROWS + b * Nn + j0;
#pragma unroll
        for (int t = 0; t < 8; t++) atomicAdd(&recv[t], col[t]);
    }
}

// ---------------------------------------------------------------------------
// charge update: c^{s+1} = c^s * (1 - decay * sigmoid(received_s - 1))
__global__ void charge_update_kernel(int s, const float* __restrict__ decay_p) {
    int r = blockIdx.x * blockDim.x + threadIdx.x;
    if (r >= NROWS) return;
    float recv = g_received[(size_t)s * NROWS + r];
    float prev = (s == 0) ? g_c0[r] : ((float*)&g_cpack[r])[s - 1];
    float sig = 1.0f / (1.0f + __expf(-(recv - 1.0f)));
    ((float*)&g_cpack[r])[s] = prev * (1.0f - (*decay_p) * sig);
}

// ---------------------------------------------------------------------------
extern "C" void kernel_launch(void* const* d_in, const int* in_sizes, int n_in,
                              void* d_out, int out_size)
{
    const float* features = (const float*)d_in[0];
    const float* W_q      = (const float*)d_in[1];
    const float* W_k      = (const float*)d_in[2];
    const float* charge_w = (const float*)d_in[3];
    const float* charge_b = (const float*)d_in[4];
    const float* ls_p     = (const float*)d_in[5];
    const float* ss_p     = (const float*)d_in[6];
    const float* decay_p  = (const float*)d_in[7];
    float* out = (float*)d_out;

    static bool attr_set = false;
    if (!attr_set) {
        cudaFuncSetAttribute(proj_mma_kernel,   cudaFuncAttributeMaxDynamicSharedMemorySize, PROJ_SMEM);
        cudaFuncSetAttribute(compat_mma_kernel, cudaFuncAttributeMaxDynamicSharedMemorySize, COMPAT_SMEM);
        attr_set = true;
    }

    convert_W_kernel<<<dim3((De * Ff) / 256, 2), 256>>>(W_q, W_k);
    convert_feat_charge_kernel<<<NROWS / 8, 256>>>(features, charge_w, charge_b);

    proj_mma_kernel<<<dim3(NROWS / 128, 2), GBLOCK, PROJ_SMEM>>>();
    compat_mma_kernel<<<dim3(2, 16, Bb), GBLOCK, COMPAT_SMEM>>>(ls_p);

    dim3 sgrid(Nn / 32, Bb);
    for (int s = 0; s < 4; s++) {
        softmax_pass_kernel<false><<<sgrid, 256>>>(s, nullptr, ss_p);
        charge_update_kernel<<<NROWS / 256, 256>>>(s, decay_p);
    }
    softmax_pass_kernel<true><<<sgrid, 256>>>(0, out, ss_p);
}

// round 8
// speedup vs baseline: 1.1369x; 1.0441x over previous
#include <cuda_runtime.h>
#include <cuda_bf16.h>
#include <math.h>
#include <stdint.h>

// Problem constants
#define Bb 4
#define Nn 2048
#define Ff 1024
#define De 128
#define NROWS (Bb*Nn)          // 8192
#define GBLOCK 256             // threads per GEMM CTA (8 warps)

// ---------------------------------------------------------------------------
// Device global scratch (no cudaMalloc allowed)
__device__ __nv_bfloat16 g_feat_hi[(size_t)NROWS * Ff];
__device__ __nv_bfloat16 g_feat_lo[(size_t)NROWS * Ff];
__device__ __nv_bfloat16 g_WT_hi[2][De * Ff];       // W^T [128 x 1024], [0]=Wq,[1]=Wk
__device__ __nv_bfloat16 g_WT_lo[2][De * Ff];
__device__ __nv_bfloat16 g_QK_hi[2][(size_t)NROWS * De];  // [0]=Q,[1]=K
__device__ __nv_bfloat16 g_QK_lo[2][(size_t)NROWS * De];
__device__ float  g_base[(size_t)Bb * Nn * Nn];     // 64 MB
__device__ float  g_c0[NROWS];
__device__ float4 g_cpack[NROWS];                   // c^1..c^4 packed, zero-padded
__device__ float  g_received[4 * NROWS];

// ---------------------------------------------------------------------------
__device__ __forceinline__ uint32_t smem_u32(const void* p) {
    uint32_t a;
    asm("{ .reg .u64 t; cvta.to.shared.u64 t, %1; cvt.u32.u64 %0, t; }" : "=r"(a) : "l"(p));
    return a;
}
__device__ __forceinline__ uint32_t sw128(uint32_t o) { return o ^ ((o >> 3) & 0x70); }

#define CP_ASYNC16(dst_u32, src_gptr) \
    asm volatile("cp.async.cg.shared.global [%0], [%1], 16;" :: "r"(dst_u32), "l"(src_gptr))
#define CP_COMMIT()  asm volatile("cp.async.commit_group;" ::: "memory")
#define CP_WAIT1()   asm volatile("cp.async.wait_group 1;" ::: "memory")
#define CP_WAIT0()   asm volatile("cp.async.wait_group 0;" ::: "memory")

#define LDMATRIX_X4(r0, r1, r2, r3, addr) \
    asm volatile("ldmatrix.sync.aligned.m8n8.x4.shared.b16 {%0,%1,%2,%3}, [%4];" \
        : "=r"(r0), "=r"(r1), "=r"(r2), "=r"(r3) : "r"(addr))

#define MMA_BF16(acc, a, b0v, b1v) \
    asm volatile("mma.sync.aligned.m16n8k16.row.col.f32.bf16.bf16.f32 " \
        "{%0,%1,%2,%3}, {%4,%5,%6,%7}, {%8,%9}, {%0,%1,%2,%3};" \
        : "+f"((acc)[0]), "+f"((acc)[1]), "+f"((acc)[2]), "+f"((acc)[3]) \
        : "r"((a)[0]), "r"((a)[1]), "r"((a)[2]), "r"((a)[3]), "r"(b0v), "r"(b1v))

// ---------------------------------------------------------------------------
// cp.async one ROWSx64 bf16 tile (rows of 128B) into SW128-swizzled smem
template<int ROWS>
__device__ __forceinline__ void cpasync_tileR(
    uint32_t dst_base, const __nv_bfloat16* src, int strideElems, int tid)
{
#pragma unroll
    for (int u = tid; u < ROWS * 8; u += GBLOCK) {
        int row = u >> 3, seg = u & 7;
        uint32_t dst = dst_base + sw128((uint32_t)(row * 128 + seg * 16));
        const __nv_bfloat16* g = src + (size_t)row * strideElems + seg * 8;
        CP_ASYNC16(dst, g);
    }
}

// Operand block layout (per 128-row x K=128 operand, hi+lo): 64KB
#define OPC_H(c) ((c) * 32768)
#define OPC_L(c) ((c) * 32768 + 16384)
#define OP_BYTES 65536

__device__ __forceinline__ void issue_op(
    uint32_t dst, const __nv_bfloat16* hi, const __nv_bfloat16* lo,
    int strideElems, int tid)
{
#pragma unroll
    for (int c = 0; c < 2; c++) {
        cpasync_tileR<128>(dst + OPC_H(c), hi + c * 64, strideElems, tid);
        cpasync_tileR<128>(dst + OPC_L(c), lo + c * 64, strideElems, tid);
    }
    CP_COMMIT();
}

// compute full K=128, 3-term bf16 split (compat): 8 warps 2Mx4N, warp 64x32
__device__ __forceinline__ void compute_tile(
    uint32_t a_base, uint32_t b_base, int tid, float acc[4][4][4])
{
    const int lane = tid & 31;
    const int wid = tid >> 5;
    const int wm = wid & 1;
    const int wn = wid >> 1;
    const int q = lane >> 3, r = lane & 7;

    const int a_row = r + ((q & 1) ? 8 : 0);
    const int a_colb = ((q & 2) ? 8 : 0) * 2;
    const int b_row = r + ((q & 2) ? 8 : 0);
    const int b_colb = ((q & 1) ? 8 : 0) * 2;

#pragma unroll
    for (int c = 0; c < 2; c++) {
#pragma unroll
        for (int ks = 0; ks < 4; ks++) {
            const int kb2 = ks * 32;

            uint32_t ah[4][4], al[4][4];
#pragma unroll
            for (int mi = 0; mi < 4; mi++) {
                uint32_t off = sw128((uint32_t)((wm * 64 + mi * 16 + a_row) * 128 + kb2 + a_colb));
                LDMATRIX_X4(ah[mi][0], ah[mi][1], ah[mi][2], ah[mi][3], a_base + OPC_H(c) + off);
                LDMATRIX_X4(al[mi][0], al[mi][1], al[mi][2], al[mi][3], a_base + OPC_L(c) + off);
            }
            uint32_t bh[2][4], bl[2][4];
#pragma unroll
            for (int p = 0; p < 2; p++) {
                uint32_t off = sw128((uint32_t)((wn * 32 + p * 16 + b_row) * 128 + kb2 + b_colb));
                LDMATRIX_X4(bh[p][0], bh[p][1], bh[p][2], bh[p][3], b_base + OPC_H(c) + off);
                LDMATRIX_X4(bl[p][0], bl[p][1], bl[p][2], bl[p][3], b_base + OPC_L(c) + off);
            }
#pragma unroll
            for (int mi = 0; mi < 4; mi++)
#pragma unroll
                for (int ni = 0; ni < 4; ni++) {
                    const int p = ni >> 1, s = (ni & 1) * 2;
                    MMA_BF16(acc[mi][ni], ah[mi], bh[p][s], bh[p][s + 1]);
                    MMA_BF16(acc[mi][ni], ah[mi], bl[p][s], bl[p][s + 1]);
                    MMA_BF16(acc[mi][ni], al[mi], bh[p][s], bh[p][s + 1]);
                }
        }
    }
}

// ---------------------------------------------------------------------------
// Fused feature convert + initial charge.
__global__ __launch_bounds__(256) void convert_feat_charge_kernel(
    const float* __restrict__ f, const float* __restrict__ cw, const float* __restrict__ cb)
{
    const int row = blockIdx.x * 8 + (threadIdx.x >> 5);
    const int lane = threadIdx.x & 31;
    const float4* fr = (const float4*)(f + (size_t)row * Ff);
    const float4* cwv = (const float4*)cw;
    __nv_bfloat162* ph = (__nv_bfloat162*)(g_feat_hi + (size_t)row * Ff);
    __nv_bfloat162* pl = (__nv_bfloat162*)(g_feat_lo + (size_t)row * Ff);

    float dot = 0.0f;
#pragma unroll
    for (int u = 0; u < 8; u++) {
        int i = lane + u * 32;
        float4 v = fr[i];
        float4 w = cwv[i];
        dot = fmaf(v.x, w.x, dot); dot = fmaf(v.y, w.y, dot);
        dot = fmaf(v.z, w.z, dot); dot = fmaf(v.w, w.w, dot);
        __nv_bfloat16 h0 = __float2bfloat16(v.x), h1 = __float2bfloat16(v.y);
        __nv_bfloat16 h2 = __float2bfloat16(v.z), h3 = __float2bfloat16(v.w);
        ph[2 * i]     = __halves2bfloat162(h0, h1);
        ph[2 * i + 1] = __halves2bfloat162(h2, h3);
        pl[2 * i]     = __halves2bfloat162(
            __float2bfloat16(v.x - __bfloat162float(h0)),
            __float2bfloat16(v.y - __bfloat162float(h1)));
        pl[2 * i + 1] = __halves2bfloat162(
            __float2bfloat16(v.z - __bfloat162float(h2)),
            __float2bfloat16(v.w - __bfloat162float(h3)));
    }
#pragma unroll
    for (int o = 16; o > 0; o >>= 1) dot += __shfl_xor_sync(0xFFFFFFFFu, dot, o);
    if (lane == 0) g_c0[row] = 1.0f / (1.0f + __expf(-(dot + cb[0])));
}

// ---------------------------------------------------------------------------
// transpose + split W; also zeroes g_received / g_cpack
__global__ void convert_W_kernel(const float* __restrict__ Wq, const float* __restrict__ Wk) {
    const float* W = (blockIdx.y == 0) ? Wq : Wk;
    int idx = blockIdx.x * blockDim.x + threadIdx.x;    // 0..131071
    int e = idx >> 10, fidx = idx & 1023;
    float x = W[(size_t)fidx * De + e];
    __nv_bfloat16 h = __float2bfloat16(x);
    g_WT_hi[blockIdx.y][idx] = h;
    g_WT_lo[blockIdx.y][idx] = __float2bfloat16(x - __bfloat162float(h));
    if (blockIdx.y == 0 && idx < 8 * NROWS) {
        if (idx < 4 * NROWS) g_received[idx] = 0.0f;
        else ((float*)g_cpack)[idx - 4 * NROWS] = 0.0f;
    }
}

// ---------------------------------------------------------------------------
// Projection GEMM: M-tile 64, grid (128, 2), 256 threads, 2 CTAs/SM.
// Stage: A 64x64 hi+lo (16KB) + B 128x64 hi+lo (32KB) = 48KB; 2 stages = 96KB.
#define PJ_A_H 0
#define PJ_A_L 8192
#define PJ_B_H 16384
#define PJ_B_L 32768
#define PJ_STAGE 49152
#define PROJ_SMEM (2 * PJ_STAGE)    // 98304

__device__ __forceinline__ void proj_issue_chunk(
    uint32_t sbuf, const __nv_bfloat16* Ah, const __nv_bfloat16* Al,
    const __nv_bfloat16* Bh, const __nv_bfloat16* Bl, int c, int tid)
{
    cpasync_tileR<64>(sbuf + PJ_A_H, Ah + c * 64, Ff, tid);
    cpasync_tileR<64>(sbuf + PJ_A_L, Al + c * 64, Ff, tid);
    cpasync_tileR<128>(sbuf + PJ_B_H, Bh + c * 64, Ff, tid);
    cpasync_tileR<128>(sbuf + PJ_B_L, Bl + c * 64, Ff, tid);
    CP_COMMIT();
}

// 8 warps: 2 in M (32 rows each) x 4 in N (32 cols); warp tile 32x32.
__device__ __forceinline__ void proj_compute_chunk(uint32_t sbuf, int tid, float acc[2][4][4])
{
    const int lane = tid & 31;
    const int wid = tid >> 5;
    const int wm = wid & 1, wn = wid >> 1;
    const int q = lane >> 3, r = lane & 7;
    const int a_row = r + ((q & 1) ? 8 : 0);
    const int a_colb = ((q & 2) ? 8 : 0) * 2;
    const int b_row = r + ((q & 2) ? 8 : 0);
    const int b_colb = ((q & 1) ? 8 : 0) * 2;

#pragma unroll
    for (int ks = 0; ks < 4; ks++) {
        const int kb2 = ks * 32;
        uint32_t ah[2][4], al[2][4];
#pragma unroll
        for (int mi = 0; mi < 2; mi++) {
            uint32_t off = sw128((uint32_t)((wm * 32 + mi * 16 + a_row) * 128 + kb2 + a_colb));
            LDMATRIX_X4(ah[mi][0], ah[mi][1], ah[mi][2], ah[mi][3], sbuf + PJ_A_H + off);
            LDMATRIX_X4(al[mi][0], al[mi][1], al[mi][2], al[mi][3], sbuf + PJ_A_L + off);
        }
        uint32_t bh[2][4], bl[2][4];
#pragma unroll
        for (int p = 0; p < 2; p++) {
            uint32_t off = sw128((uint32_t)((wn * 32 + p * 16 + b_row) * 128 + kb2 + b_colb));
            LDMATRIX_X4(bh[p][0], bh[p][1], bh[p][2], bh[p][3], sbuf + PJ_B_H + off);
            LDMATRIX_X4(bl[p][0], bl[p][1], bl[p][2], bl[p][3], sbuf + PJ_B_L + off);
        }
#pragma unroll
        for (int mi = 0; mi < 2; mi++)
#pragma unroll
            for (int ni = 0; ni < 4; ni++) {
                const int p = ni >> 1, s = (ni & 1) * 2;
                MMA_BF16(acc[mi][ni], ah[mi], bh[p][s], bh[p][s + 1]);
                MMA_BF16(acc[mi][ni], ah[mi], bl[p][s], bl[p][s + 1]);
                MMA_BF16(acc[mi][ni], al[mi], bh[p][s], bh[p][s + 1]);
            }
    }
}

__global__ __launch_bounds__(GBLOCK, 2) void proj_mma_kernel() {
    extern __shared__ __align__(1024) char smem[];
    const int tid = threadIdx.x;
    const int y = blockIdx.y;
    const int mBase = blockIdx.x * 64;
    uint32_t sb = smem_u32(smem);

    const __nv_bfloat16* Ah = g_feat_hi + (size_t)mBase * Ff;
    const __nv_bfloat16* Al = g_feat_lo + (size_t)mBase * Ff;
    const __nv_bfloat16* Bh = g_WT_hi[y];
    const __nv_bfloat16* Bl = g_WT_lo[y];

    float acc[2][4][4];
#pragma unroll
    for (int mi = 0; mi < 2; mi++)
#pragma unroll
        for (int ni = 0; ni < 4; ni++)
#pragma unroll
            for (int k = 0; k < 4; k++) acc[mi][ni][k] = 0.0f;

    const int CHUNKS = 16;
    proj_issue_chunk(sb + 0 * PJ_STAGE, Ah, Al, Bh, Bl, 0, tid);
    proj_issue_chunk(sb + 1 * PJ_STAGE, Ah, Al, Bh, Bl, 1, tid);

#pragma unroll 1
    for (int c = 0; c < CHUNKS; c++) {
        if (c + 1 < CHUNKS) { CP_WAIT1(); } else { CP_WAIT0(); }
        __syncthreads();                          // stage c ready
        proj_compute_chunk(sb + (c & 1) * PJ_STAGE, tid, acc);
        __syncthreads();                          // all warps done with stage c
        if (c + 2 < CHUNKS)
            proj_issue_chunk(sb + (c & 1) * PJ_STAGE, Ah, Al, Bh, Bl, c + 2, tid);
    }

    const int lane = tid & 31, wid = tid >> 5;
    const int wm = wid & 1, wn = wid >> 1;
    const int g = lane >> 2, t2 = (lane & 3) * 2;
    __nv_bfloat16* ph = g_QK_hi[y];
    __nv_bfloat16* pl = g_QK_lo[y];
#pragma unroll
    for (int mi = 0; mi < 2; mi++)
#pragma unroll
        for (int ni = 0; ni < 4; ni++) {
            const int cc = wn * 32 + ni * 8 + t2;
#pragma unroll
            for (int half = 0; half < 2; half++) {
                const int rr = mBase + wm * 32 + mi * 16 + g + half * 8;
                float v0 = acc[mi][ni][half * 2], v1 = acc[mi][ni][half * 2 + 1];
                __nv_bfloat16 h0 = __float2bfloat16(v0), h1 = __float2bfloat16(v1);
                __nv_bfloat16 l0 = __float2bfloat16(v0 - __bfloat162float(h0));
                __nv_bfloat16 l1 = __float2bfloat16(v1 - __bfloat162float(h1));
                *(__nv_bfloat162*)(ph + (size_t)rr * De + cc) = __halves2bfloat162(h0, h1);
                *(__nv_bfloat162*)(pl + (size_t)rr * De + cc) = __halves2bfloat162(l0, l1);
            }
        }
}

// ---------------------------------------------------------------------------
// compat GEMM, persistent-j (unchanged from round 7 structure)
#define COMPAT_SMEM (1024 + 3 * OP_BYTES)   // 197632
__global__ __launch_bounds__(GBLOCK, 1) void compat_mma_kernel(const float* __restrict__ ls_p) {
    extern __shared__ __align__(1024) char smem[];
    const int tid = threadIdx.x;
    const int jh = blockIdx.x;           // 0..1
    const int iBase = blockIdx.y * 128;  // 16 i-tiles
    const int b = blockIdx.z;
    uint32_t sb = smem_u32(smem);
    const uint32_t A  = sb + 1024;
    const uint32_t B0 = A + OP_BYTES;
    const uint32_t B1 = B0 + OP_BYTES;

    const __nv_bfloat16* Ah = g_QK_hi[0] + (size_t)(b * Nn + iBase) * De;
    const __nv_bfloat16* Al = g_QK_lo[0] + (size_t)(b * Nn + iBase) * De;
    const __nv_bfloat16* Kh = g_QK_hi[1] + (size_t)(b * Nn + jh * 1024) * De;
    const __nv_bfloat16* Kl = g_QK_lo[1] + (size_t)(b * Nn + jh * 1024) * De;

    issue_op(A,  Ah, Al, De, tid);
    issue_op(B0, Kh,            Kl,            De, tid);
    issue_op(B1, Kh + 128 * De, Kl + 128 * De, De, tid);
    CP_WAIT1();
    __syncthreads();

    const float ls = *ls_p;
    const float rsqrtD = 0.08838834764831845f;
    const int lane = tid & 31, wid = tid >> 5;
    const int wm = wid & 1, wn = wid >> 1;
    const int g = lane >> 2, t2 = (lane & 3) * 2;

#pragma unroll 1
    for (int j = 0; j < 8; j++) {
        const uint32_t Bcur = (j & 1) ? B1 : B0;

        float acc[4][4][4];
#pragma unroll
        for (int mi = 0; mi < 4; mi++)
#pragma unroll
            for (int ni = 0; ni < 4; ni++)
#pragma unroll
                for (int k = 0; k < 4; k++) acc[mi][ni][k] = 0.0f;

        compute_tile(A, Bcur, tid, acc);

        const int jBase = jh * 1024 + j * 128;
#pragma unroll
        for (int mi = 0; mi < 4; mi++)
#pragma unroll
            for (int ni = 0; ni < 4; ni++) {
                const int col = jBase + wn * 32 + ni * 8 + t2;
#pragma unroll
                for (int half = 0; half < 2; half++) {
                    const int row = iBase + wm * 64 + mi * 16 + g + half * 8;
                    float d0 = fmaxf(fabsf((float)(row - col)), 1.0f);
                    float d1 = fmaxf(fabsf((float)(row - col - 1)), 1.0f);
                    float2 v;
                    v.x = acc[mi][ni][half * 2]     * rsqrtD + __fdividef(ls, d0);
                    v.y = acc[mi][ni][half * 2 + 1] * rsqrtD + __fdividef(ls, d1);
                    *(float2*)(g_base + ((size_t)(b * Nn + row)) * Nn + col) = v;
                }
            }

        __syncthreads();
        if (j + 2 < 8) {
            issue_op(Bcur, Kh + (size_t)(j + 2) * 128 * De,
                           Kl + (size_t)(j + 2) * 128 * De, De, tid);
            CP_WAIT1();
            __syncthreads();
        } else if (j + 1 < 8) {
            CP_WAIT0();
            __syncthreads();
        }
    }
}

// ---------------------------------------------------------------------------
// Softmax pass: logits = base * (1 + ss * dot4(c_i, c_j)); 4-row groups,
// double-buffered reduction slots, next-group register prefetch.
__device__ __forceinline__ void sm_load_group(
    int b, int i0, int j0, float bb[4][8])
{
#pragma unroll
    for (int rr = 0; rr < 4; rr++) {
        const float4* p = (const float4*)(g_base + ((size_t)(b * Nn + i0 + rr)) * Nn + j0);
        float4 v0 = p[0], v1 = p[1];
        bb[rr][0] = v0.x; bb[rr][1] = v0.y; bb[rr][2] = v0.z; bb[rr][3] = v0.w;
        bb[rr][4] = v1.x; bb[rr][5] = v1.y; bb[rr][6] = v1.z; bb[rr][7] = v1.w;
    }
}

template<bool WRITE_OUT>
__global__ __launch_bounds__(256) void softmax_pass_kernel(
    int s, float* __restrict__ out, const float* __restrict__ ss_p)
{
    __shared__ float s_red[2][4][8];
    const int b = blockIdx.y;
    const int rowBase = blockIdx.x * 32;
    const int tid = threadIdx.x, lane = tid & 31, wid = tid >> 5;
    const float ss = *ss_p;
    const int j0 = tid * 8;

    float4 cj[8];
#pragma unroll
    for (int t = 0; t < 8; t++) cj[t] = g_cpack[b * Nn + j0 + t];

    float col[8];
#pragma unroll
    for (int t = 0; t < 8; t++) col[t] = 0.0f;

    float bb[4][8];
    sm_load_group(b, rowBase, j0, bb);

#pragma unroll 1
    for (int g = 0; g < 8; g++) {
        const int i0 = rowBase + g * 4;
        float nbb[4][8];
        if (g < 7) sm_load_group(b, i0 + 4, j0, nbb);

        float lsum[4];
#pragma unroll
        for (int rr = 0; rr < 4; rr++) {
            float4 ci = g_cpack[b * Nn + i0 + rr];
            float cx = ci.x * ss, cy = ci.y * ss, cz = ci.z * ss, cw = ci.w * ss;
            float acc = 0.0f;
#pragma unroll
            for (int t = 0; t < 8; t++) {
                float m = 1.0f;
                m = fmaf(cx, cj[t].x, m);
                m = fmaf(cy, cj[t].y, m);
                m = fmaf(cz, cj[t].z, m);
                m = fmaf(cw, cj[t].w, m);
                float e = __expf(bb[rr][t] * m);
                bb[rr][t] = e;
                acc += e;
            }
            lsum[rr] = acc;
        }
#pragma unroll
        for (int o = 16; o > 0; o >>= 1) {
#pragma unroll
            for (int rr = 0; rr < 4; rr++)
                lsum[rr] += __shfl_xor_sync(0xFFFFFFFFu, lsum[rr], o);
        }
        if (lane == 0) {
#pragma unroll
            for (int rr = 0; rr < 4; rr++) s_red[g & 1][rr][wid] = lsum[rr];
        }
        __syncthreads();

#pragma unroll
        for (int rr = 0; rr < 4; rr++) {
            float tot = s_red[g & 1][rr][0];
#pragma unroll
            for (int w = 1; w < 8; w++) tot += s_red[g & 1][rr][w];
            float inv = __fdividef(1.0f, tot);
            if (WRITE_OUT) {
                float4* orow = (float4*)(out + ((size_t)(b * Nn + i0 + rr)) * Nn + j0);
                orow[0] = make_float4(bb[rr][0] * inv, bb[rr][1] * inv, bb[rr][2] * inv, bb[rr][3] * inv);
                orow[1] = make_float4(bb[rr][4] * inv, bb[rr][5] * inv, bb[rr][6] * inv, bb[rr][7] * inv);
            } else {
#pragma unroll
                for (int t = 0; t < 8; t++) col[t] = fmaf(bb[rr][t], inv, col[t]);
            }
        }

        if (g < 7) {
#pragma unroll
            for (int rr = 0; rr < 4; rr++)
#pragma unroll
                for (int t = 0; t < 8; t++) bb[rr][t] = nbb[rr][t];
        }
    }
    if (!WRITE_OUT) {
        float* recv = g_received + (size_t)s * NROWS + b * Nn + j0;
#pragma unroll
        for (int t = 0; t < 8; t++) atomicAdd(&recv[t], col[t]);
    }
}

// ---------------------------------------------------------------------------
// charge update: c^{s+1} = c^s * (1 - decay * sigmoid(received_s - 1))
__global__ void charge_update_kernel(int s, const float* __restrict__ decay_p) {
    int r = blockIdx.x * blockDim.x + threadIdx.x;
    if (r >= NROWS) return;
    float recv = g_received[(size_t)s * NROWS + r];
    float prev = (s == 0) ? g_c0[r] : ((float*)&g_cpack[r])[s - 1];
    float sig = 1.0f / (1.0f + __expf(-(recv - 1.0f)));
    ((float*)&g_cpack[r])[s] = prev * (1.0f - (*decay_p) * sig);
}

// ---------------------------------------------------------------------------
extern "C" void kernel_launch(void* const* d_in, const int* in_sizes, int n_in,
                              void* d_out, int out_size)
{
    const float* features = (const float*)d_in[0];
    const float* W_q      = (const float*)d_in[1];
    const float* W_k      = (const float*)d_in[2];
    const float* charge_w = (const float*)d_in[3];
    const float* charge_b = (const float*)d_in[4];
    const float* ls_p     = (const float*)d_in[5];
    const float* ss_p     = (const float*)d_in[6];
    const float* decay_p  = (const float*)d_in[7];
    float* out = (float*)d_out;

    static bool attr_set = false;
    if (!attr_set) {
        cudaFuncSetAttribute(proj_mma_kernel,   cudaFuncAttributeMaxDynamicSharedMemorySize, PROJ_SMEM);
        cudaFuncSetAttribute(compat_mma_kernel, cudaFuncAttributeMaxDynamicSharedMemorySize, COMPAT_SMEM);
        attr_set = true;
    }

    convert_W_kernel<<<dim3((De * Ff) / 256, 2), 256>>>(W_q, W_k);
    convert_feat_charge_kernel<<<NROWS / 8, 256>>>(features, charge_w, charge_b);

    proj_mma_kernel<<<dim3(NROWS / 64, 2), GBLOCK, PROJ_SMEM>>>();
    compat_mma_kernel<<<dim3(2, 16, Bb), GBLOCK, COMPAT_SMEM>>>(ls_p);

    dim3 sgrid(Nn / 32, Bb);
    for (int s = 0; s < 4; s++) {
        softmax_pass_kernel<false><<<sgrid, 256>>>(s, nullptr, ss_p);
        charge_update_kernel<<<NROWS / 256, 256>>>(s, decay_p);
    }
    softmax_pass_kernel<true><<<sgrid, 256>>>(0, out, ss_p);
}